// round 15
// baseline (speedup 1.0000x reference)
#include <cuda_runtime.h>
#include <cuda_fp16.h>
#include <cstdint>

#define TDIM 8192
#define DDIM 4096

// ---- device scratch (allocation-free rule: __device__ globals) ----
static __device__ __half g_w1[(size_t)DDIM * DDIM];
static __device__ __half g_w2[(size_t)DDIM * DDIM];
static __device__ __half g_a[(size_t)TDIM * DDIM];
static __device__ __half g_h[(size_t)TDIM * DDIM];

// E2M1 decode via PRMT: positive magnitudes {0,.5,1,1.5,2,3,4,6} have fp16
// high bytes {00,38,3C,3E,40,42,44,46}; sign = code bit 3. Scale is a power
// of two in [2^-6, 2^1]; fp16 multiply is exact here.
__device__ __forceinline__ uint4 dequant_convert(const int4 c0, const int4 c1,
                                                 const float s) {
    const __half2 hs2 = __half2half2(__float2half_rn(s));
    uint4 o;
    {
        uint32_t sel = (c0.x & 7) | ((c0.y & 7) << 4) | ((c0.z & 7) << 8) |
                       ((c0.w & 7) << 12);
        uint32_t hb = __byte_perm(0x3E3C3800u, 0x46444240u, sel);
        uint32_t p0 = __byte_perm(hb, 0, 0x1404) |
                      ((c0.x & 8) << 12) | ((c0.y & 8) << 28);
        uint32_t p1 = __byte_perm(hb, 0, 0x3424) |
                      ((c0.z & 8) << 12) | ((c0.w & 8) << 28);
        __half2 r0 = __hmul2(*reinterpret_cast<__half2*>(&p0), hs2);
        __half2 r1 = __hmul2(*reinterpret_cast<__half2*>(&p1), hs2);
        o.x = *reinterpret_cast<uint32_t*>(&r0);
        o.y = *reinterpret_cast<uint32_t*>(&r1);
    }
    {
        uint32_t sel = (c1.x & 7) | ((c1.y & 7) << 4) | ((c1.z & 7) << 8) |
                       ((c1.w & 7) << 12);
        uint32_t hb = __byte_perm(0x3E3C3800u, 0x46444240u, sel);
        uint32_t p0 = __byte_perm(hb, 0, 0x1404) |
                      ((c1.x & 8) << 12) | ((c1.y & 8) << 28);
        uint32_t p1 = __byte_perm(hb, 0, 0x3424) |
                      ((c1.z & 8) << 12) | ((c1.w & 8) << 28);
        __half2 r0 = __hmul2(*reinterpret_cast<__half2*>(&p0), hs2);
        __half2 r1 = __hmul2(*reinterpret_cast<__half2*>(&p1), hs2);
        o.z = *reinterpret_cast<uint32_t*>(&r0);
        o.w = *reinterpret_cast<uint32_t*>(&r1);
    }
    return o;
}

__device__ __forceinline__ void dequant8(const int* __restrict__ codes,
                                         const float* __restrict__ scales,
                                         __half* __restrict__ out,
                                         size_t base) {
    const int4 c0 = *reinterpret_cast<const int4*>(codes + base);
    const int4 c1 = *reinterpret_cast<const int4*>(codes + base + 4);
    float s = __ldg(scales + (base >> 12) * (DDIM / 32) + ((base & 4095) >> 5));
    *reinterpret_cast<uint4*>(out + base) = dequant_convert(c0, c1, s);
}

// ---- aux kernel: dequant W1 + convert x (W2 dequant lives in gemm0) ----
#define DQ_BLOCKS ((DDIM * (size_t)DDIM / 8) / 256)   // 8192
#define SP_BLOCKS ((TDIM * (size_t)DDIM / 8) / 256)   // 16384
__global__ void aux_kernel(const int* __restrict__ w1c, const float* __restrict__ w1s,
                           const float* __restrict__ x) {
    const size_t b = blockIdx.x;
    if (b < DQ_BLOCKS) {
        dequant8(w1c, w1s, g_w1, (b * 256 + threadIdx.x) * 8);
    } else {
        size_t base = ((b - DQ_BLOCKS) * 256 + threadIdx.x) * 8;
        float4 v0 = *reinterpret_cast<const float4*>(x + base);
        float4 v1 = *reinterpret_cast<const float4*>(x + base + 4);
        uint4 o;
        __half2 h;
        h = __floats2half2_rn(v0.x, v0.y); o.x = *reinterpret_cast<uint32_t*>(&h);
        h = __floats2half2_rn(v0.z, v0.w); o.y = *reinterpret_cast<uint32_t*>(&h);
        h = __floats2half2_rn(v1.x, v1.y); o.z = *reinterpret_cast<uint32_t*>(&h);
        h = __floats2half2_rn(v1.z, v1.w); o.w = *reinterpret_cast<uint32_t*>(&h);
        *reinterpret_cast<uint4*>(g_a + base) = o;
    }
}

__device__ __forceinline__ void ldmat4(uint32_t addr, uint32_t& d0, uint32_t& d1,
                                       uint32_t& d2, uint32_t& d3) {
    asm volatile("ldmatrix.sync.aligned.m8n8.x4.shared.b16 {%0,%1,%2,%3}, [%4];\n"
                 : "=r"(d0), "=r"(d1), "=r"(d2), "=r"(d3) : "r"(addr));
}

__device__ __forceinline__ void mma16816(float* c, const uint32_t* a, const uint32_t* b) {
    asm volatile(
        "mma.sync.aligned.m16n8k16.row.col.f32.f16.f16.f32 "
        "{%0,%1,%2,%3}, {%4,%5,%6,%7}, {%8,%9}, {%0,%1,%2,%3};\n"
        : "+f"(c[0]), "+f"(c[1]), "+f"(c[2]), "+f"(c[3])
        : "r"(a[0]), "r"(a[1]), "r"(a[2]), "r"(a[3]), "r"(b[0]), "r"(b[1]));
}

__device__ __forceinline__ void cp16(uint32_t saddr, const void* gaddr) {
    asm volatile("cp.async.cg.shared.global [%0], [%1], 16;\n"
                 :: "r"(saddr), "l"(gaddr));
}

// ====== GEMM: 128(M) x 128(N) CTA, 128 threads, 2 CTAs/SM, BK=64, 3 stages =
// 4 warps = 2(M) x 2(N), 64x64 per warp. Rotating stage offsets (no %).
// smem rows: 128B, chunk ^= (row & 7): conflict-free ldmatrix + writes.
// LAYER 0: W2 dequant software-pipelined across chunks 0..8 — unit k's LDGs
// issue at chunk k, convert+STG at chunk k+1 (loads are ~2048 cyc old: no stall).
#define BK 64
#define STAGES 3
#define NCH (DDIM / BK)
#define W_BYTES (128 * BK * 2)
#define A_BYTES (128 * BK * 2)
#define STAGE_BYTES (W_BYTES + A_BYTES)
#define SMEM_BYTES (STAGES * STAGE_BYTES)

template <int LAYER>
__global__ void __launch_bounds__(128, 2)
gemm_kernel(const float* __restrict__ bias, float* __restrict__ outf,
            const int* __restrict__ w2c, const float* __restrict__ w2s) {
    extern __shared__ char dsm[];
    const __half* __restrict__ A = (LAYER == 0) ? g_a : g_h;
    const __half* __restrict__ W = (LAYER == 0) ? g_w1 : g_w2;

    __shared__ float sBias[128];

    const int tid = threadIdx.x;
    const int lane = tid & 31;
    const int wid = tid >> 5;
    const int wm = wid & 1;
    const int wn = wid >> 1;
    const int o0 = blockIdx.x * 128;
    const int t0 = blockIdx.y * 128;

    sBias[tid] = __ldg(bias + o0 + tid);

    const uint32_t sdyn = (uint32_t)__cvta_generic_to_shared(dsm);

    // ---- coalesced loader maps: 8 threads cover one row's 128B ----
    const int lc = tid & 7;
    const int lr = tid >> 3;
    const __half* pW = W + (size_t)(o0 + lr) * DDIM + lc * 8;
    const __half* pA = A + (size_t)(t0 + lr) * DDIM + lc * 8;
    uint32_t st[8];
#pragma unroll
    for (int s = 0; s < 8; s++) {
        int row = lr + 16 * s;
        st[s] = (uint32_t)(row * 128 + ((lc ^ (row & 7)) << 4));
    }

    // ---- mma fragment address components ----
    const int aRow = lane & 15;
    const int aKC = lane >> 4;
    const int bRow = (lane & 7) + ((lane >> 4) << 3);
    const int bKC = (lane >> 3) & 1;
    uint32_t aOff[4];
    int aXor[4];
#pragma unroll
    for (int mf = 0; mf < 4; mf++) {
        int row = wm * 64 + mf * 16 + aRow;
        aOff[mf] = (uint32_t)(row * 128);
        aXor[mf] = row & 7;
    }
    uint32_t bOff[4];
    int bXor[4];
#pragma unroll
    for (int nb = 0; nb < 4; nb++) {
        int row = wn * 64 + nb * 16 + bRow;
        bOff[nb] = (uint32_t)(row * 128);
        bXor[nb] = row & 7;
    }

    float acc[4][8][4];
#pragma unroll
    for (int i = 0; i < 4; i++)
#pragma unroll
        for (int j = 0; j < 8; j++)
#pragma unroll
            for (int k = 0; k < 4; k++) acc[i][j][k] = 0.f;

    // double-buffered fragments
    uint32_t af[2][4][4], bf[2][8][2];

    auto ldB = [&](int buf, uint32_t wb, int nb, int kc) {
        uint32_t addr = wb + bOff[nb] + (uint32_t)(((kc + bKC) ^ bXor[nb]) << 4);
        ldmat4(addr, bf[buf][nb * 2][0], bf[buf][nb * 2][1], bf[buf][nb * 2 + 1][0],
               bf[buf][nb * 2 + 1][1]);
    };
    auto ldA = [&](int buf, uint32_t ab, int mf, int kc) {
        uint32_t addr = ab + aOff[mf] + (uint32_t)(((kc + aKC) ^ aXor[mf]) << 4);
        ldmat4(addr, af[buf][mf][0], af[buf][mf][1], af[buf][mf][2], af[buf][mf][3]);
    };
    auto mma8 = [&](int mf, int buf) {
#pragma unroll
        for (int nf = 0; nf < 8; nf++) mma16816(acc[mf][nf], af[buf][mf], bf[buf][nf]);
    };

    // full-stage loader (prologue only)
    auto load_stage = [&](uint32_t wb, int k0) {
        const uint32_t ab = wb + W_BYTES;
#pragma unroll
        for (int q = 0; q < 8; q++)
            cp16(wb + st[q], pW + k0 + (size_t)q * 16 * DDIM);
#pragma unroll
        for (int q = 0; q < 8; q++)
            cp16(ab + st[q], pA + k0 + (size_t)q * 16 * DDIM);
        asm volatile("cp.async.commit_group;\n" ::: "memory");
    };

    // prologue: chunks 0,1 in flight; wait chunk0; preload kstep0 frags (buf0)
    load_stage(sdyn, 0);
    load_stage(sdyn + STAGE_BYTES, BK);
    asm volatile("cp.async.wait_group 1;\n" ::: "memory");
    __syncthreads();
#pragma unroll
    for (int nb = 0; nb < 4; nb++) ldB(0, sdyn, nb, 0);
#pragma unroll
    for (int mf = 0; mf < 4; mf++) ldA(0, sdyn + W_BYTES, mf, 0);

    // W2-dequant pipeline state (LAYER 0 only)
    const size_t dqSlice =
        ((size_t)blockIdx.y * (DDIM / 128) + blockIdx.x) * 8192 + tid * 8;
    int4 dqc0, dqc1;
    float dqs;
    size_t dqBase = 0;

    // rotating stage bases: wb = compute, wbn = next (visible), wbL = load dst
    uint32_t wb = sdyn;
    uint32_t wbn = sdyn + STAGE_BYTES;
    uint32_t wbL = sdyn + 2 * STAGE_BYTES;
    const __half* pWL = pW + 2 * BK;
    const __half* pAL = pA + 2 * BK;

#pragma unroll 1
    for (int i = 0; i < NCH; i++) {
        // ---- W2 dequant pipeline: store unit i-1, load unit i ----
        if (LAYER == 0 && i <= 8) {
            if (i >= 1)
                *reinterpret_cast<uint4*>(g_w2 + dqBase) =
                    dequant_convert(dqc0, dqc1, dqs);
            if (i < 8) {
                dqBase = dqSlice + (size_t)i * 1024;
                dqc0 = *reinterpret_cast<const int4*>(w2c + dqBase);
                dqc1 = *reinterpret_cast<const int4*>(w2c + dqBase + 4);
                dqs = __ldg(w2s + (dqBase >> 12) * (DDIM / 32) +
                            ((dqBase & 4095) >> 5));
            }
        }

        const uint32_t ab = wb + W_BYTES;
        const uint32_t abn = wbn + W_BYTES;
        const uint32_t abL = wbL + W_BYTES;
        const bool haveNext = (i + 1 < NCH);
        const bool load2 = (i + 2 < NCH);

        // ---- ksteps 0..2: next-kstep frags + 16 cp.async spread under MMA ----
#pragma unroll
        for (int j = 0; j < 3; j++) {
            const int cur = j & 1;
            const int nxt = cur ^ 1;
            const int kcN = 2 * (j + 1);
            ldB(nxt, wb, 0, kcN);
            ldB(nxt, wb, 1, kcN);
            mma8(0, cur);
            if (load2) {
                if (j == 0) {
                    cp16(wbL + st[0], pWL);
                    cp16(wbL + st[1], pWL + (size_t)16 * DDIM);
                    cp16(wbL + st[2], pWL + (size_t)32 * DDIM);
                } else if (j == 1) {
                    cp16(wbL + st[6], pWL + (size_t)96 * DDIM);
                    cp16(wbL + st[7], pWL + (size_t)112 * DDIM);
                    cp16(abL + st[0], pAL);
                } else {
                    cp16(abL + st[4], pAL + (size_t)64 * DDIM);
                    cp16(abL + st[5], pAL + (size_t)80 * DDIM);
                }
            }
            ldB(nxt, wb, 2, kcN);
            ldB(nxt, wb, 3, kcN);
            mma8(1, cur);
            if (load2) {
                if (j == 0) {
                    cp16(wbL + st[3], pWL + (size_t)48 * DDIM);
                    cp16(wbL + st[4], pWL + (size_t)64 * DDIM);
                    cp16(wbL + st[5], pWL + (size_t)80 * DDIM);
                } else if (j == 1) {
                    cp16(abL + st[1], pAL + (size_t)16 * DDIM);
                    cp16(abL + st[2], pAL + (size_t)32 * DDIM);
                    cp16(abL + st[3], pAL + (size_t)48 * DDIM);
                } else {
                    cp16(abL + st[6], pAL + (size_t)96 * DDIM);
                    cp16(abL + st[7], pAL + (size_t)112 * DDIM);
                }
            }
            ldA(nxt, ab, 0, kcN);
            ldA(nxt, ab, 1, kcN);
            mma8(2, cur);
            ldA(nxt, ab, 2, kcN);
            ldA(nxt, ab, 3, kcN);
            mma8(3, cur);
            if (j == 2 && load2)
                asm volatile("cp.async.commit_group;\n" ::: "memory");
        }

        // ---- kstep 3 (frags in buf1): barrier mid-burst, preload next chunk ----
        mma8(0, 1);
        mma8(1, 1);
        if (load2)
            asm volatile("cp.async.wait_group 1;\n" ::: "memory");
        else
            asm volatile("cp.async.wait_group 0;\n" ::: "memory");
        __syncthreads();
        if (haveNext) {
            ldB(0, wbn, 0, 0);
            ldB(0, wbn, 1, 0);
        }
        mma8(2, 1);
        if (haveNext) {
            ldB(0, wbn, 2, 0);
            ldB(0, wbn, 3, 0);
            ldA(0, abn, 0, 0);
            ldA(0, abn, 1, 0);
        }
        mma8(3, 1);
        if (haveNext) {
            ldA(0, abn, 2, 0);
            ldA(0, abn, 3, 0);
        }

        // rotate stages, advance load pointers
        uint32_t tmp = wb;
        wb = wbn;
        wbn = wbL;
        wbL = tmp;
        pWL += BK;
        pAL += BK;
    }

    // ---- epilogue ----
    const int gr = lane >> 2;
    const int tc2 = (lane & 3) * 2;
#pragma unroll
    for (int mf = 0; mf < 4; mf++) {
        const int row = t0 + wm * 64 + mf * 16 + gr;
#pragma unroll
        for (int nf = 0; nf < 8; nf++) {
            const int colL = wn * 64 + nf * 8 + tc2;
            const int col = o0 + colL;
            float bv0 = sBias[colL];
            float bv1 = sBias[colL + 1];
            float v00 = acc[mf][nf][0] + bv0;
            float v01 = acc[mf][nf][1] + bv1;
            float v10 = acc[mf][nf][2] + bv0;
            float v11 = acc[mf][nf][3] + bv1;
            if (LAYER == 0) {
                *reinterpret_cast<__half2*>(g_h + (size_t)row * DDIM + col) =
                    __floats2half2_rn(v00, v01);
                *reinterpret_cast<__half2*>(g_h + (size_t)(row + 8) * DDIM + col) =
                    __floats2half2_rn(v10, v11);
            } else {
                *reinterpret_cast<float2*>(outf + (size_t)row * DDIM + col) =
                    make_float2(v00, v01);
                *reinterpret_cast<float2*>(outf + (size_t)(row + 8) * DDIM + col) =
                    make_float2(v10, v11);
            }
        }
    }
}

extern "C" void kernel_launch(void* const* d_in, const int* in_sizes, int n_in,
                              void* d_out, int out_size) {
    const float* x = (const float*)d_in[0];
    const int* w1c = (const int*)d_in[1];
    const float* w1s = (const float*)d_in[2];
    const float* b1 = (const float*)d_in[3];
    const int* w2c = (const int*)d_in[4];
    const float* w2s = (const float*)d_in[5];
    const float* b2 = (const float*)d_in[6];
    float* out = (float*)d_out;

    cudaFuncSetAttribute(gemm_kernel<0>, cudaFuncAttributeMaxDynamicSharedMemorySize,
                         SMEM_BYTES);
    cudaFuncSetAttribute(gemm_kernel<1>, cudaFuncAttributeMaxDynamicSharedMemorySize,
                         SMEM_BYTES);

    aux_kernel<<<(unsigned)(DQ_BLOCKS + SP_BLOCKS), 256>>>(w1c, w1s, x);

    dim3 grid(DDIM / 128, TDIM / 128);
    gemm_kernel<0><<<grid, 128, SMEM_BYTES>>>(b1, nullptr, w2c, w2s);
    gemm_kernel<1><<<grid, 128, SMEM_BYTES>>>(b2, out, nullptr, nullptr);
}

// round 16
// speedup vs baseline: 1.0037x; 1.0037x over previous
#include <cuda_runtime.h>
#include <cuda_fp16.h>
#include <cstdint>

#define TDIM 8192
#define DDIM 4096

// ---- device scratch (allocation-free rule: __device__ globals) ----
static __device__ __half g_w1[(size_t)DDIM * DDIM];
static __device__ __half g_w2[(size_t)DDIM * DDIM];
static __device__ __half g_a[(size_t)TDIM * DDIM];
static __device__ __half g_h[(size_t)TDIM * DDIM];

// E2M1 decode via PRMT: positive magnitudes {0,.5,1,1.5,2,3,4,6} have fp16
// high bytes {00,38,3C,3E,40,42,44,46}; sign = code bit 3. Scale is a power
// of two in [2^-6, 2^1]; fp16 multiply is exact here.
__device__ __forceinline__ void dequant8(const int* __restrict__ codes,
                                         const float* __restrict__ scales,
                                         __half* __restrict__ out,
                                         size_t base) {
    const int4 c0 = *reinterpret_cast<const int4*>(codes + base);
    const int4 c1 = *reinterpret_cast<const int4*>(codes + base + 4);
    float s = __ldg(scales + (base >> 12) * (DDIM / 32) + ((base & 4095) >> 5));
    const __half2 hs2 = __half2half2(__float2half_rn(s));
    uint4 o;
    {
        uint32_t sel = (c0.x & 7) | ((c0.y & 7) << 4) | ((c0.z & 7) << 8) |
                       ((c0.w & 7) << 12);
        uint32_t hb = __byte_perm(0x3E3C3800u, 0x46444240u, sel);
        uint32_t p0 = __byte_perm(hb, 0, 0x1404) |
                      ((c0.x & 8) << 12) | ((c0.y & 8) << 28);
        uint32_t p1 = __byte_perm(hb, 0, 0x3424) |
                      ((c0.z & 8) << 12) | ((c0.w & 8) << 28);
        __half2 r0 = __hmul2(*reinterpret_cast<__half2*>(&p0), hs2);
        __half2 r1 = __hmul2(*reinterpret_cast<__half2*>(&p1), hs2);
        o.x = *reinterpret_cast<uint32_t*>(&r0);
        o.y = *reinterpret_cast<uint32_t*>(&r1);
    }
    {
        uint32_t sel = (c1.x & 7) | ((c1.y & 7) << 4) | ((c1.z & 7) << 8) |
                       ((c1.w & 7) << 12);
        uint32_t hb = __byte_perm(0x3E3C3800u, 0x46444240u, sel);
        uint32_t p0 = __byte_perm(hb, 0, 0x1404) |
                      ((c1.x & 8) << 12) | ((c1.y & 8) << 28);
        uint32_t p1 = __byte_perm(hb, 0, 0x3424) |
                      ((c1.z & 8) << 12) | ((c1.w & 8) << 28);
        __half2 r0 = __hmul2(*reinterpret_cast<__half2*>(&p0), hs2);
        __half2 r1 = __hmul2(*reinterpret_cast<__half2*>(&p1), hs2);
        o.z = *reinterpret_cast<uint32_t*>(&r0);
        o.w = *reinterpret_cast<uint32_t*>(&r1);
    }
    *reinterpret_cast<uint4*>(out + base) = o;
}

// ---- aux kernel: dequant W1 + convert x, 16 elems/thread ----
#define DQ_BLOCKS ((DDIM * (size_t)DDIM / 16) / 256)   // 4096
#define SP_BLOCKS ((TDIM * (size_t)DDIM / 16) / 256)   // 8192
__global__ void aux_kernel(const int* __restrict__ w1c, const float* __restrict__ w1s,
                           const float* __restrict__ x) {
    const size_t b = blockIdx.x;
    if (b < DQ_BLOCKS) {
        size_t base = (b * 256 + threadIdx.x) * 16;
        dequant8(w1c, w1s, g_w1, base);
        dequant8(w1c, w1s, g_w1, base + 8);
    } else {
        size_t base = ((b - DQ_BLOCKS) * 256 + threadIdx.x) * 16;
#pragma unroll
        for (int u = 0; u < 2; u++) {
            float4 v0 = *reinterpret_cast<const float4*>(x + base + u * 8);
            float4 v1 = *reinterpret_cast<const float4*>(x + base + u * 8 + 4);
            uint4 o;
            __half2 h;
            h = __floats2half2_rn(v0.x, v0.y); o.x = *reinterpret_cast<uint32_t*>(&h);
            h = __floats2half2_rn(v0.z, v0.w); o.y = *reinterpret_cast<uint32_t*>(&h);
            h = __floats2half2_rn(v1.x, v1.y); o.z = *reinterpret_cast<uint32_t*>(&h);
            h = __floats2half2_rn(v1.z, v1.w); o.w = *reinterpret_cast<uint32_t*>(&h);
            *reinterpret_cast<uint4*>(g_a + base + u * 8) = o;
        }
    }
}

__device__ __forceinline__ void ldmat4(uint32_t addr, uint32_t& d0, uint32_t& d1,
                                       uint32_t& d2, uint32_t& d3) {
    asm volatile("ldmatrix.sync.aligned.m8n8.x4.shared.b16 {%0,%1,%2,%3}, [%4];\n"
                 : "=r"(d0), "=r"(d1), "=r"(d2), "=r"(d3) : "r"(addr));
}

__device__ __forceinline__ void mma16816(float* c, const uint32_t* a, const uint32_t* b) {
    asm volatile(
        "mma.sync.aligned.m16n8k16.row.col.f32.f16.f16.f32 "
        "{%0,%1,%2,%3}, {%4,%5,%6,%7}, {%8,%9}, {%0,%1,%2,%3};\n"
        : "+f"(c[0]), "+f"(c[1]), "+f"(c[2]), "+f"(c[3])
        : "r"(a[0]), "r"(a[1]), "r"(a[2]), "r"(a[3]), "r"(b[0]), "r"(b[1]));
}

__device__ __forceinline__ void cp16(uint32_t saddr, const void* gaddr) {
    asm volatile("cp.async.cg.shared.global [%0], [%1], 16;\n"
                 :: "r"(saddr), "l"(gaddr));
}

// ====== GEMM: 128(M) x 128(N) CTA, 128 threads, 2 CTAs/SM, BK=64, 3 stages =
// 4 warps = 2(M) x 2(N), 64x64 per warp. Rotating stage offsets (no %).
// smem rows: 128B, chunk ^= (row & 7): conflict-free ldmatrix + writes.
// LAYER 0 dequants its 8192-element slice of W2 during the prologue
// (overlaps DRAM-bound work under tensor-bound gemm0; R14-proven form).
#define BK 64
#define STAGES 3
#define NCH (DDIM / BK)
#define W_BYTES (128 * BK * 2)
#define A_BYTES (128 * BK * 2)
#define STAGE_BYTES (W_BYTES + A_BYTES)
#define SMEM_BYTES (STAGES * STAGE_BYTES)

template <int LAYER>
__global__ void __launch_bounds__(128, 2)
gemm_kernel(const float* __restrict__ bias, float* __restrict__ outf,
            const int* __restrict__ w2c, const float* __restrict__ w2s) {
    extern __shared__ char dsm[];
    const __half* __restrict__ A = (LAYER == 0) ? g_a : g_h;
    const __half* __restrict__ W = (LAYER == 0) ? g_w1 : g_w2;

    __shared__ float sBias[128];

    const int tid = threadIdx.x;
    const int lane = tid & 31;
    const int wid = tid >> 5;
    const int wm = wid & 1;
    const int wn = wid >> 1;
    const int o0 = blockIdx.x * 128;
    const int t0 = blockIdx.y * 128;

    sBias[tid] = __ldg(bias + o0 + tid);

    const uint32_t sdyn = (uint32_t)__cvta_generic_to_shared(dsm);

    // ---- coalesced loader maps: 8 threads cover one row's 128B ----
    const int lc = tid & 7;
    const int lr = tid >> 3;
    const __half* pW = W + (size_t)(o0 + lr) * DDIM + lc * 8;
    const __half* pA = A + (size_t)(t0 + lr) * DDIM + lc * 8;
    uint32_t st[8];
#pragma unroll
    for (int s = 0; s < 8; s++) {
        int row = lr + 16 * s;
        st[s] = (uint32_t)(row * 128 + ((lc ^ (row & 7)) << 4));
    }

    // ---- mma fragment address components ----
    const int aRow = lane & 15;
    const int aKC = lane >> 4;
    const int bRow = (lane & 7) + ((lane >> 4) << 3);
    const int bKC = (lane >> 3) & 1;
    uint32_t aOff[4];
    int aXor[4];
#pragma unroll
    for (int mf = 0; mf < 4; mf++) {
        int row = wm * 64 + mf * 16 + aRow;
        aOff[mf] = (uint32_t)(row * 128);
        aXor[mf] = row & 7;
    }
    uint32_t bOff[4];
    int bXor[4];
#pragma unroll
    for (int nb = 0; nb < 4; nb++) {
        int row = wn * 64 + nb * 16 + bRow;
        bOff[nb] = (uint32_t)(row * 128);
        bXor[nb] = row & 7;
    }

    float acc[4][8][4];
#pragma unroll
    for (int i = 0; i < 4; i++)
#pragma unroll
        for (int j = 0; j < 8; j++)
#pragma unroll
            for (int k = 0; k < 4; k++) acc[i][j][k] = 0.f;

    // double-buffered fragments
    uint32_t af[2][4][4], bf[2][8][2];

    auto ldB = [&](int buf, uint32_t wb, int nb, int kc) {
        uint32_t addr = wb + bOff[nb] + (uint32_t)(((kc + bKC) ^ bXor[nb]) << 4);
        ldmat4(addr, bf[buf][nb * 2][0], bf[buf][nb * 2][1], bf[buf][nb * 2 + 1][0],
               bf[buf][nb * 2 + 1][1]);
    };
    auto ldA = [&](int buf, uint32_t ab, int mf, int kc) {
        uint32_t addr = ab + aOff[mf] + (uint32_t)(((kc + aKC) ^ aXor[mf]) << 4);
        ldmat4(addr, af[buf][mf][0], af[buf][mf][1], af[buf][mf][2], af[buf][mf][3]);
    };
    auto mma8 = [&](int mf, int buf) {
#pragma unroll
        for (int nf = 0; nf < 8; nf++) mma16816(acc[mf][nf], af[buf][mf], bf[buf][nf]);
    };

    // full-stage loader (prologue only)
    auto load_stage = [&](uint32_t wb, int k0) {
        const uint32_t ab = wb + W_BYTES;
#pragma unroll
        for (int q = 0; q < 8; q++)
            cp16(wb + st[q], pW + k0 + (size_t)q * 16 * DDIM);
#pragma unroll
        for (int q = 0; q < 8; q++)
            cp16(ab + st[q], pA + k0 + (size_t)q * 16 * DDIM);
        asm volatile("cp.async.commit_group;\n" ::: "memory");
    };

    // prologue: chunks 0,1 in flight
    load_stage(sdyn, 0);
    load_stage(sdyn + STAGE_BYTES, BK);

    // LAYER 0: dequant this CTA's slice of W2 while prologue tiles are in
    // flight (DRAM-bound work under tensor-bound gemm0; gemm1 consumes it
    // after the kernel boundary).
    if (LAYER == 0) {
        const size_t slice = ((size_t)blockIdx.y * (DDIM / 128) + blockIdx.x) * 8192;
#pragma unroll
        for (int k = 0; k < 8; k++)
            dequant8(w2c, w2s, g_w2, slice + (size_t)k * 1024 + tid * 8);
    }

    asm volatile("cp.async.wait_group 1;\n" ::: "memory");
    __syncthreads();
#pragma unroll
    for (int nb = 0; nb < 4; nb++) ldB(0, sdyn, nb, 0);
#pragma unroll
    for (int mf = 0; mf < 4; mf++) ldA(0, sdyn + W_BYTES, mf, 0);

    // rotating stage bases: wb = compute, wbn = next (visible), wbL = load dst
    uint32_t wb = sdyn;
    uint32_t wbn = sdyn + STAGE_BYTES;
    uint32_t wbL = sdyn + 2 * STAGE_BYTES;
    const __half* pWL = pW + 2 * BK;
    const __half* pAL = pA + 2 * BK;

#pragma unroll 1
    for (int i = 0; i < NCH; i++) {
        const uint32_t ab = wb + W_BYTES;
        const uint32_t abn = wbn + W_BYTES;
        const uint32_t abL = wbL + W_BYTES;
        const bool haveNext = (i + 1 < NCH);
        const bool load2 = (i + 2 < NCH);

        // ---- ksteps 0..2: next-kstep frags + 16 cp.async spread under MMA ----
#pragma unroll
        for (int j = 0; j < 3; j++) {
            const int cur = j & 1;
            const int nxt = cur ^ 1;
            const int kcN = 2 * (j + 1);
            ldB(nxt, wb, 0, kcN);
            ldB(nxt, wb, 1, kcN);
            mma8(0, cur);
            if (load2) {
                if (j == 0) {
                    cp16(wbL + st[0], pWL);
                    cp16(wbL + st[1], pWL + (size_t)16 * DDIM);
                    cp16(wbL + st[2], pWL + (size_t)32 * DDIM);
                } else if (j == 1) {
                    cp16(wbL + st[6], pWL + (size_t)96 * DDIM);
                    cp16(wbL + st[7], pWL + (size_t)112 * DDIM);
                    cp16(abL + st[0], pAL);
                } else {
                    cp16(abL + st[4], pAL + (size_t)64 * DDIM);
                    cp16(abL + st[5], pAL + (size_t)80 * DDIM);
                }
            }
            ldB(nxt, wb, 2, kcN);
            ldB(nxt, wb, 3, kcN);
            mma8(1, cur);
            if (load2) {
                if (j == 0) {
                    cp16(wbL + st[3], pWL + (size_t)48 * DDIM);
                    cp16(wbL + st[4], pWL + (size_t)64 * DDIM);
                    cp16(wbL + st[5], pWL + (size_t)80 * DDIM);
                } else if (j == 1) {
                    cp16(abL + st[1], pAL + (size_t)16 * DDIM);
                    cp16(abL + st[2], pAL + (size_t)32 * DDIM);
                    cp16(abL + st[3], pAL + (size_t)48 * DDIM);
                } else {
                    cp16(abL + st[6], pAL + (size_t)96 * DDIM);
                    cp16(abL + st[7], pAL + (size_t)112 * DDIM);
                }
            }
            ldA(nxt, ab, 0, kcN);
            ldA(nxt, ab, 1, kcN);
            mma8(2, cur);
            ldA(nxt, ab, 2, kcN);
            ldA(nxt, ab, 3, kcN);
            mma8(3, cur);
            if (j == 2 && load2)
                asm volatile("cp.async.commit_group;\n" ::: "memory");
        }

        // ---- kstep 3 (frags in buf1): barrier mid-burst, preload next chunk ----
        mma8(0, 1);
        mma8(1, 1);
        if (load2)
            asm volatile("cp.async.wait_group 1;\n" ::: "memory");
        else
            asm volatile("cp.async.wait_group 0;\n" ::: "memory");
        __syncthreads();
        if (haveNext) {
            ldB(0, wbn, 0, 0);
            ldB(0, wbn, 1, 0);
        }
        mma8(2, 1);
        if (haveNext) {
            ldB(0, wbn, 2, 0);
            ldB(0, wbn, 3, 0);
            ldA(0, abn, 0, 0);
            ldA(0, abn, 1, 0);
        }
        mma8(3, 1);
        if (haveNext) {
            ldA(0, abn, 2, 0);
            ldA(0, abn, 3, 0);
        }

        // rotate stages, advance load pointers
        uint32_t tmp = wb;
        wb = wbn;
        wbn = wbL;
        wbL = tmp;
        pWL += BK;
        pAL += BK;
    }

    // ---- epilogue ----
    const int gr = lane >> 2;
    const int tc2 = (lane & 3) * 2;
#pragma unroll
    for (int mf = 0; mf < 4; mf++) {
        const int row = t0 + wm * 64 + mf * 16 + gr;
#pragma unroll
        for (int nf = 0; nf < 8; nf++) {
            const int colL = wn * 64 + nf * 8 + tc2;
            const int col = o0 + colL;
            float bv0 = sBias[colL];
            float bv1 = sBias[colL + 1];
            float v00 = acc[mf][nf][0] + bv0;
            float v01 = acc[mf][nf][1] + bv1;
            float v10 = acc[mf][nf][2] + bv0;
            float v11 = acc[mf][nf][3] + bv1;
            if (LAYER == 0) {
                *reinterpret_cast<__half2*>(g_h + (size_t)row * DDIM + col) =
                    __floats2half2_rn(v00, v01);
                *reinterpret_cast<__half2*>(g_h + (size_t)(row + 8) * DDIM + col) =
                    __floats2half2_rn(v10, v11);
            } else {
                *reinterpret_cast<float2*>(outf + (size_t)row * DDIM + col) =
                    make_float2(v00, v01);
                *reinterpret_cast<float2*>(outf + (size_t)(row + 8) * DDIM + col) =
                    make_float2(v10, v11);
            }
        }
    }
}

extern "C" void kernel_launch(void* const* d_in, const int* in_sizes, int n_in,
                              void* d_out, int out_size) {
    const float* x = (const float*)d_in[0];
    const int* w1c = (const int*)d_in[1];
    const float* w1s = (const float*)d_in[2];
    const float* b1 = (const float*)d_in[3];
    const int* w2c = (const int*)d_in[4];
    const float* w2s = (const float*)d_in[5];
    const float* b2 = (const float*)d_in[6];
    float* out = (float*)d_out;

    cudaFuncSetAttribute(gemm_kernel<0>, cudaFuncAttributeMaxDynamicSharedMemorySize,
                         SMEM_BYTES);
    cudaFuncSetAttribute(gemm_kernel<1>, cudaFuncAttributeMaxDynamicSharedMemorySize,
                         SMEM_BYTES);

    aux_kernel<<<(unsigned)(DQ_BLOCKS + SP_BLOCKS), 256>>>(w1c, w1s, x);

    dim3 grid(DDIM / 128, TDIM / 128);
    gemm_kernel<0><<<grid, 128, SMEM_BYTES>>>(b1, nullptr, w2c, w2s);
    gemm_kernel<1><<<grid, 128, SMEM_BYTES>>>(b2, out, nullptr, nullptr);
}

// round 17
// speedup vs baseline: 1.0062x; 1.0025x over previous
#include <cuda_runtime.h>
#include <cuda_fp16.h>
#include <cstdint>

#define TDIM 8192
#define DDIM 4096

// ---- device scratch (allocation-free rule: __device__ globals) ----
static __device__ __half g_w1[(size_t)DDIM * DDIM];
static __device__ __half g_w2[(size_t)DDIM * DDIM];
static __device__ __half g_a[(size_t)TDIM * DDIM];
static __device__ __half g_h[(size_t)TDIM * DDIM];

// E2M1 decode via PRMT: positive magnitudes {0,.5,1,1.5,2,3,4,6} have fp16
// high bytes {00,38,3C,3E,40,42,44,46}; sign = code bit 3. Scale is a power
// of two in [2^-6, 2^1]; fp16 multiply is exact here.
__device__ __forceinline__ uint4 dequant_convert(const int4 c0, const int4 c1,
                                                 const float s) {
    const __half2 hs2 = __half2half2(__float2half_rn(s));
    uint4 o;
    {
        uint32_t sel = (c0.x & 7) | ((c0.y & 7) << 4) | ((c0.z & 7) << 8) |
                       ((c0.w & 7) << 12);
        uint32_t hb = __byte_perm(0x3E3C3800u, 0x46444240u, sel);
        uint32_t p0 = __byte_perm(hb, 0, 0x1404) |
                      ((c0.x & 8) << 12) | ((c0.y & 8) << 28);
        uint32_t p1 = __byte_perm(hb, 0, 0x3424) |
                      ((c0.z & 8) << 12) | ((c0.w & 8) << 28);
        __half2 r0 = __hmul2(*reinterpret_cast<__half2*>(&p0), hs2);
        __half2 r1 = __hmul2(*reinterpret_cast<__half2*>(&p1), hs2);
        o.x = *reinterpret_cast<uint32_t*>(&r0);
        o.y = *reinterpret_cast<uint32_t*>(&r1);
    }
    {
        uint32_t sel = (c1.x & 7) | ((c1.y & 7) << 4) | ((c1.z & 7) << 8) |
                       ((c1.w & 7) << 12);
        uint32_t hb = __byte_perm(0x3E3C3800u, 0x46444240u, sel);
        uint32_t p0 = __byte_perm(hb, 0, 0x1404) |
                      ((c1.x & 8) << 12) | ((c1.y & 8) << 28);
        uint32_t p1 = __byte_perm(hb, 0, 0x3424) |
                      ((c1.z & 8) << 12) | ((c1.w & 8) << 28);
        __half2 r0 = __hmul2(*reinterpret_cast<__half2*>(&p0), hs2);
        __half2 r1 = __hmul2(*reinterpret_cast<__half2*>(&p1), hs2);
        o.z = *reinterpret_cast<uint32_t*>(&r0);
        o.w = *reinterpret_cast<uint32_t*>(&r1);
    }
    return o;
}

__device__ __forceinline__ void dequant8(const int* __restrict__ codes,
                                         const float* __restrict__ scales,
                                         __half* __restrict__ out,
                                         size_t base) {
    const int4 c0 = *reinterpret_cast<const int4*>(codes + base);
    const int4 c1 = *reinterpret_cast<const int4*>(codes + base + 4);
    float s = __ldg(scales + (base >> 12) * (DDIM / 32) + ((base & 4095) >> 5));
    *reinterpret_cast<uint4*>(out + base) = dequant_convert(c0, c1, s);
}

// ---- aux kernel: dequant W1 + convert x, 8 elems/thread (R14 form) ----
#define DQ_BLOCKS ((DDIM * (size_t)DDIM / 8) / 256)   // 8192
#define SP_BLOCKS ((TDIM * (size_t)DDIM / 8) / 256)   // 16384
__global__ void aux_kernel(const int* __restrict__ w1c, const float* __restrict__ w1s,
                           const float* __restrict__ x) {
    const size_t b = blockIdx.x;
    if (b < DQ_BLOCKS) {
        dequant8(w1c, w1s, g_w1, (b * 256 + threadIdx.x) * 8);
    } else {
        size_t base = ((b - DQ_BLOCKS) * 256 + threadIdx.x) * 8;
        float4 v0 = *reinterpret_cast<const float4*>(x + base);
        float4 v1 = *reinterpret_cast<const float4*>(x + base + 4);
        uint4 o;
        __half2 h;
        h = __floats2half2_rn(v0.x, v0.y); o.x = *reinterpret_cast<uint32_t*>(&h);
        h = __floats2half2_rn(v0.z, v0.w); o.y = *reinterpret_cast<uint32_t*>(&h);
        h = __floats2half2_rn(v1.x, v1.y); o.z = *reinterpret_cast<uint32_t*>(&h);
        h = __floats2half2_rn(v1.z, v1.w); o.w = *reinterpret_cast<uint32_t*>(&h);
        *reinterpret_cast<uint4*>(g_a + base) = o;
    }
}

__device__ __forceinline__ void ldmat4(uint32_t addr, uint32_t& d0, uint32_t& d1,
                                       uint32_t& d2, uint32_t& d3) {
    asm volatile("ldmatrix.sync.aligned.m8n8.x4.shared.b16 {%0,%1,%2,%3}, [%4];\n"
                 : "=r"(d0), "=r"(d1), "=r"(d2), "=r"(d3) : "r"(addr));
}

__device__ __forceinline__ void mma16816(float* c, const uint32_t* a, const uint32_t* b) {
    asm volatile(
        "mma.sync.aligned.m16n8k16.row.col.f32.f16.f16.f32 "
        "{%0,%1,%2,%3}, {%4,%5,%6,%7}, {%8,%9}, {%0,%1,%2,%3};\n"
        : "+f"(c[0]), "+f"(c[1]), "+f"(c[2]), "+f"(c[3])
        : "r"(a[0]), "r"(a[1]), "r"(a[2]), "r"(a[3]), "r"(b[0]), "r"(b[1]));
}

__device__ __forceinline__ void cp16(uint32_t saddr, const void* gaddr) {
    asm volatile("cp.async.cg.shared.global [%0], [%1], 16;\n"
                 :: "r"(saddr), "l"(gaddr));
}

// ====== GEMM: 128(M) x 128(N) CTA, 128 threads, 2 CTAs/SM, BK=64, 3 stages =
// 4 warps = 2(M) x 2(N), 64x64 per warp. Rotating stage offsets (no %).
// smem rows: 128B, chunk ^= (row & 7): conflict-free ldmatrix + writes.
// LAYER 0 dequants its 8192-element slice of W2 during the prologue, in two
// MLP=4 batches (loads issued back-to-back to amortize DRAM latency).
#define BK 64
#define STAGES 3
#define NCH (DDIM / BK)
#define W_BYTES (128 * BK * 2)
#define A_BYTES (128 * BK * 2)
#define STAGE_BYTES (W_BYTES + A_BYTES)
#define SMEM_BYTES (STAGES * STAGE_BYTES)

template <int LAYER>
__global__ void __launch_bounds__(128, 2)
gemm_kernel(const float* __restrict__ bias, float* __restrict__ outf,
            const int* __restrict__ w2c, const float* __restrict__ w2s) {
    extern __shared__ char dsm[];
    const __half* __restrict__ A = (LAYER == 0) ? g_a : g_h;
    const __half* __restrict__ W = (LAYER == 0) ? g_w1 : g_w2;

    __shared__ float sBias[128];

    const int tid = threadIdx.x;
    const int lane = tid & 31;
    const int wid = tid >> 5;
    const int wm = wid & 1;
    const int wn = wid >> 1;
    const int o0 = blockIdx.x * 128;
    const int t0 = blockIdx.y * 128;

    sBias[tid] = __ldg(bias + o0 + tid);

    const uint32_t sdyn = (uint32_t)__cvta_generic_to_shared(dsm);

    // ---- coalesced loader maps: 8 threads cover one row's 128B ----
    const int lc = tid & 7;
    const int lr = tid >> 3;
    const __half* pW = W + (size_t)(o0 + lr) * DDIM + lc * 8;
    const __half* pA = A + (size_t)(t0 + lr) * DDIM + lc * 8;
    uint32_t st[8];
#pragma unroll
    for (int s = 0; s < 8; s++) {
        int row = lr + 16 * s;
        st[s] = (uint32_t)(row * 128 + ((lc ^ (row & 7)) << 4));
    }

    // ---- mma fragment address components ----
    const int aRow = lane & 15;
    const int aKC = lane >> 4;
    const int bRow = (lane & 7) + ((lane >> 4) << 3);
    const int bKC = (lane >> 3) & 1;
    uint32_t aOff[4];
    int aXor[4];
#pragma unroll
    for (int mf = 0; mf < 4; mf++) {
        int row = wm * 64 + mf * 16 + aRow;
        aOff[mf] = (uint32_t)(row * 128);
        aXor[mf] = row & 7;
    }
    uint32_t bOff[4];
    int bXor[4];
#pragma unroll
    for (int nb = 0; nb < 4; nb++) {
        int row = wn * 64 + nb * 16 + bRow;
        bOff[nb] = (uint32_t)(row * 128);
        bXor[nb] = row & 7;
    }

    float acc[4][8][4];
#pragma unroll
    for (int i = 0; i < 4; i++)
#pragma unroll
        for (int j = 0; j < 8; j++)
#pragma unroll
            for (int k = 0; k < 4; k++) acc[i][j][k] = 0.f;

    // double-buffered fragments
    uint32_t af[2][4][4], bf[2][8][2];

    auto ldB = [&](int buf, uint32_t wb, int nb, int kc) {
        uint32_t addr = wb + bOff[nb] + (uint32_t)(((kc + bKC) ^ bXor[nb]) << 4);
        ldmat4(addr, bf[buf][nb * 2][0], bf[buf][nb * 2][1], bf[buf][nb * 2 + 1][0],
               bf[buf][nb * 2 + 1][1]);
    };
    auto ldA = [&](int buf, uint32_t ab, int mf, int kc) {
        uint32_t addr = ab + aOff[mf] + (uint32_t)(((kc + aKC) ^ aXor[mf]) << 4);
        ldmat4(addr, af[buf][mf][0], af[buf][mf][1], af[buf][mf][2], af[buf][mf][3]);
    };
    auto mma8 = [&](int mf, int buf) {
#pragma unroll
        for (int nf = 0; nf < 8; nf++) mma16816(acc[mf][nf], af[buf][mf], bf[buf][nf]);
    };

    // full-stage loader (prologue only)
    auto load_stage = [&](uint32_t wb, int k0) {
        const uint32_t ab = wb + W_BYTES;
#pragma unroll
        for (int q = 0; q < 8; q++)
            cp16(wb + st[q], pW + k0 + (size_t)q * 16 * DDIM);
#pragma unroll
        for (int q = 0; q < 8; q++)
            cp16(ab + st[q], pA + k0 + (size_t)q * 16 * DDIM);
        asm volatile("cp.async.commit_group;\n" ::: "memory");
    };

    // prologue: chunks 0,1 in flight
    load_stage(sdyn, 0);
    load_stage(sdyn + STAGE_BYTES, BK);

    // LAYER 0: dequant this CTA's 8192-elem slice of W2 while prologue tiles
    // are in flight. Two MLP=4 batches: 4 units' loads issue back-to-back,
    // then convert+store — exposed DRAM latency ~2 round-trips, not 8.
    if (LAYER == 0) {
        const size_t slice =
            ((size_t)blockIdx.y * (DDIM / 128) + blockIdx.x) * 8192 + tid * 8;
#pragma unroll
        for (int h = 0; h < 2; h++) {
            int4 c0[4], c1[4];
            float s[4];
#pragma unroll
            for (int k = 0; k < 4; k++) {
                size_t base = slice + (size_t)(h * 4 + k) * 1024;
                c0[k] = *reinterpret_cast<const int4*>(w2c + base);
                c1[k] = *reinterpret_cast<const int4*>(w2c + base + 4);
                s[k] = __ldg(w2s + (base >> 12) * (DDIM / 32) +
                             ((base & 4095) >> 5));
            }
#pragma unroll
            for (int k = 0; k < 4; k++) {
                size_t base = slice + (size_t)(h * 4 + k) * 1024;
                *reinterpret_cast<uint4*>(g_w2 + base) =
                    dequant_convert(c0[k], c1[k], s[k]);
            }
        }
    }

    asm volatile("cp.async.wait_group 1;\n" ::: "memory");
    __syncthreads();
#pragma unroll
    for (int nb = 0; nb < 4; nb++) ldB(0, sdyn, nb, 0);
#pragma unroll
    for (int mf = 0; mf < 4; mf++) ldA(0, sdyn + W_BYTES, mf, 0);

    // rotating stage bases: wb = compute, wbn = next (visible), wbL = load dst
    uint32_t wb = sdyn;
    uint32_t wbn = sdyn + STAGE_BYTES;
    uint32_t wbL = sdyn + 2 * STAGE_BYTES;
    const __half* pWL = pW + 2 * BK;
    const __half* pAL = pA + 2 * BK;

#pragma unroll 1
    for (int i = 0; i < NCH; i++) {
        const uint32_t ab = wb + W_BYTES;
        const uint32_t abn = wbn + W_BYTES;
        const uint32_t abL = wbL + W_BYTES;
        const bool haveNext = (i + 1 < NCH);
        const bool load2 = (i + 2 < NCH);

        // ---- ksteps 0..2: next-kstep frags + 16 cp.async spread under MMA ----
#pragma unroll
        for (int j = 0; j < 3; j++) {
            const int cur = j & 1;
            const int nxt = cur ^ 1;
            const int kcN = 2 * (j + 1);
            ldB(nxt, wb, 0, kcN);
            ldB(nxt, wb, 1, kcN);
            mma8(0, cur);
            if (load2) {
                if (j == 0) {
                    cp16(wbL + st[0], pWL);
                    cp16(wbL + st[1], pWL + (size_t)16 * DDIM);
                    cp16(wbL + st[2], pWL + (size_t)32 * DDIM);
                } else if (j == 1) {
                    cp16(wbL + st[6], pWL + (size_t)96 * DDIM);
                    cp16(wbL + st[7], pWL + (size_t)112 * DDIM);
                    cp16(abL + st[0], pAL);
                } else {
                    cp16(abL + st[4], pAL + (size_t)64 * DDIM);
                    cp16(abL + st[5], pAL + (size_t)80 * DDIM);
                }
            }
            ldB(nxt, wb, 2, kcN);
            ldB(nxt, wb, 3, kcN);
            mma8(1, cur);
            if (load2) {
                if (j == 0) {
                    cp16(wbL + st[3], pWL + (size_t)48 * DDIM);
                    cp16(wbL + st[4], pWL + (size_t)64 * DDIM);
                    cp16(wbL + st[5], pWL + (size_t)80 * DDIM);
                } else if (j == 1) {
                    cp16(abL + st[1], pAL + (size_t)16 * DDIM);
                    cp16(abL + st[2], pAL + (size_t)32 * DDIM);
                    cp16(abL + st[3], pAL + (size_t)48 * DDIM);
                } else {
                    cp16(abL + st[6], pAL + (size_t)96 * DDIM);
                    cp16(abL + st[7], pAL + (size_t)112 * DDIM);
                }
            }
            ldA(nxt, ab, 0, kcN);
            ldA(nxt, ab, 1, kcN);
            mma8(2, cur);
            ldA(nxt, ab, 2, kcN);
            ldA(nxt, ab, 3, kcN);
            mma8(3, cur);
            if (j == 2 && load2)
                asm volatile("cp.async.commit_group;\n" ::: "memory");
        }

        // ---- kstep 3 (frags in buf1): barrier mid-burst, preload next chunk ----
        mma8(0, 1);
        mma8(1, 1);
        if (load2)
            asm volatile("cp.async.wait_group 1;\n" ::: "memory");
        else
            asm volatile("cp.async.wait_group 0;\n" ::: "memory");
        __syncthreads();
        if (haveNext) {
            ldB(0, wbn, 0, 0);
            ldB(0, wbn, 1, 0);
        }
        mma8(2, 1);
        if (haveNext) {
            ldB(0, wbn, 2, 0);
            ldB(0, wbn, 3, 0);
            ldA(0, abn, 0, 0);
            ldA(0, abn, 1, 0);
        }
        mma8(3, 1);
        if (haveNext) {
            ldA(0, abn, 2, 0);
            ldA(0, abn, 3, 0);
        }

        // rotate stages, advance load pointers
        uint32_t tmp = wb;
        wb = wbn;
        wbn = wbL;
        wbL = tmp;
        pWL += BK;
        pAL += BK;
    }

    // ---- epilogue ----
    const int gr = lane >> 2;
    const int tc2 = (lane & 3) * 2;
#pragma unroll
    for (int mf = 0; mf < 4; mf++) {
        const int row = t0 + wm * 64 + mf * 16 + gr;
#pragma unroll
        for (int nf = 0; nf < 8; nf++) {
            const int colL = wn * 64 + nf * 8 + tc2;
            const int col = o0 + colL;
            float bv0 = sBias[colL];
            float bv1 = sBias[colL + 1];
            float v00 = acc[mf][nf][0] + bv0;
            float v01 = acc[mf][nf][1] + bv1;
            float v10 = acc[mf][nf][2] + bv0;
            float v11 = acc[mf][nf][3] + bv1;
            if (LAYER == 0) {
                *reinterpret_cast<__half2*>(g_h + (size_t)row * DDIM + col) =
                    __floats2half2_rn(v00, v01);
                *reinterpret_cast<__half2*>(g_h + (size_t)(row + 8) * DDIM + col) =
                    __floats2half2_rn(v10, v11);
            } else {
                *reinterpret_cast<float2*>(outf + (size_t)row * DDIM + col) =
                    make_float2(v00, v01);
                *reinterpret_cast<float2*>(outf + (size_t)(row + 8) * DDIM + col) =
                    make_float2(v10, v11);
            }
        }
    }
}

extern "C" void kernel_launch(void* const* d_in, const int* in_sizes, int n_in,
                              void* d_out, int out_size) {
    const float* x = (const float*)d_in[0];
    const int* w1c = (const int*)d_in[1];
    const float* w1s = (const float*)d_in[2];
    const float* b1 = (const float*)d_in[3];
    const int* w2c = (const int*)d_in[4];
    const float* w2s = (const float*)d_in[5];
    const float* b2 = (const float*)d_in[6];
    float* out = (float*)d_out;

    cudaFuncSetAttribute(gemm_kernel<0>, cudaFuncAttributeMaxDynamicSharedMemorySize,
                         SMEM_BYTES);
    cudaFuncSetAttribute(gemm_kernel<1>, cudaFuncAttributeMaxDynamicSharedMemorySize,
                         SMEM_BYTES);

    aux_kernel<<<(unsigned)(DQ_BLOCKS + SP_BLOCKS), 256>>>(w1c, w1s, x);

    dim3 grid(DDIM / 128, TDIM / 128);
    gemm_kernel<0><<<grid, 128, SMEM_BYTES>>>(b1, nullptr, w2c, w2s);
    gemm_kernel<1><<<grid, 128, SMEM_BYTES>>>(b2, out, nullptr, nullptr);
}